// round 12
// baseline (speedup 1.0000x reference)
#include <cuda_runtime.h>
#include <cuda_fp16.h>
#include <cstdint>

// ---------------- problem constants ---------------------------------------
#define BATCH 8
#define AGENTS 6
#define IMGS 48
#define CH 256
#define HH 32
#define WW 32
#define HW 1024
#define CIN1 512
#define COUT 768
#define NITER 3
#define PP 34            // padded H/W
#define PCH 512          // channels in padded NHWC activation array

// ---------------- device scratch (allocation is forbidden) ----------------
static __device__ __align__(16) __half g_P[(size_t)IMGS * PP * PP * PCH];
static __device__ __align__(16) __half g_wih_hi[(size_t)9 * COUT * CIN1];
static __device__ __align__(16) __half g_wih_lo[(size_t)9 * COUT * CIN1];
static __device__ __align__(16) __half g_whh_hi[(size_t)9 * COUT * CH];
static __device__ __align__(16) __half g_whh_lo[(size_t)9 * COUT * CH];
static __device__ __align__(16) float g_gi[(size_t)IMGS * COUT * HW];
static __device__ __align__(16) float g_gh[(size_t)IMGS * COUT * HW];

// ---------------- helpers ---------------------------------------------------
__device__ __forceinline__ uint32_t smem_u32(const void* p) {
    uint32_t a;
    asm("{ .reg .u64 t; cvta.to.shared.u64 t, %1; cvt.u32.u64 %0, t; }"
        : "=r"(a) : "l"(p));
    return a;
}
__device__ __forceinline__ void cp16(uint32_t smem, const void* g) {
    asm volatile("cp.async.cg.shared.global [%0], [%1], 16;"
                 :: "r"(smem), "l"(g));
}
#define CP_COMMIT() asm volatile("cp.async.commit_group;" ::: "memory")
template <int N>
__device__ __forceinline__ void cp_wait() {
    asm volatile("cp.async.wait_group %0;" :: "n"(N) : "memory");
}
__device__ __forceinline__ void ldsm4(uint32_t& r0, uint32_t& r1, uint32_t& r2,
                                      uint32_t& r3, uint32_t addr) {
    asm volatile("ldmatrix.sync.aligned.m8n8.x4.shared.b16 {%0,%1,%2,%3}, [%4];"
                 : "=r"(r0), "=r"(r1), "=r"(r2), "=r"(r3) : "r"(addr));
}
__device__ __forceinline__ void mma_fp16(float* d, const uint32_t* a,
                                         const uint32_t* b) {
    asm volatile(
        "mma.sync.aligned.m16n8k16.row.col.f32.f16.f16.f32 "
        "{%0,%1,%2,%3},{%4,%5,%6,%7},{%8,%9},{%0,%1,%2,%3};"
        : "+f"(d[0]), "+f"(d[1]), "+f"(d[2]), "+f"(d[3])
        : "r"(a[0]), "r"(a[1]), "r"(a[2]), "r"(a[3]), "r"(b[0]), "r"(b[1]));
}

// ---------------- prep: weight split/transpose to [tap][oc][ci] ------------
__global__ void wprep_kernel(const float* __restrict__ w_ih,
                             const float* __restrict__ w_hh) {
    int idx = blockIdx.x * blockDim.x + threadIdx.x;
    const int n1 = 9 * COUT * CIN1;
    if (idx < n1) {
        int t = idx / (COUT * CIN1);
        int rem = idx - t * (COUT * CIN1);
        int oc = rem / CIN1;
        int ci = rem - oc * CIN1;
        float v = w_ih[((size_t)oc * CIN1 + ci) * 9 + t];
        __half h = __float2half(v);
        g_wih_hi[idx] = h;
        g_wih_lo[idx] = __float2half(v - __half2float(h));
    }
    const int n2 = 9 * COUT * CH;
    if (idx < n2) {
        int t = idx / (COUT * CH);
        int rem = idx - t * (COUT * CH);
        int oc = rem / CH;
        int ci = rem - oc * CH;
        float v = w_hh[((size_t)oc * CH + ci) * 9 + t];
        __half h = __float2half(v);
        g_whh_hi[idx] = h;
        g_whh_lo[idx] = __float2half(v - __half2float(h));
    }
}

// ---------------- zero padded borders --------------------------------------
__global__ void zero_border_kernel() {
    int idx = blockIdx.x * blockDim.x + threadIdx.x;   // img*1156*64
    int g = idx & 63;
    int pix = (idx >> 6) % (PP * PP);
    int img = idx / (64 * PP * PP);
    if (img >= IMGS) return;
    int pp = pix / PP, qq = pix % PP;
    if (pp != 0 && pp != PP - 1 && qq != 0 && qq != PP - 1) return;
    size_t off = ((size_t)(img * PP * PP) + pix) * PCH + g * 8;
    float4 z = make_float4(0.f, 0.f, 0.f, 0.f);
    *(float4*)&g_P[off] = z;
}

// ---------------- build padded NHWC fp16 from NCHW fp32 --------------------
__global__ void build_nhwc_kernel(const float* __restrict__ src) {
    __shared__ float s[AGENTS][32][33];
    const int tid = threadIdx.x;
    const int px0 = blockIdx.x * 32;
    const int c0 = blockIdx.y * 32;
    const int b = blockIdx.z;

#pragma unroll
    for (int a = 0; a < AGENTS; ++a) {
        for (int e = tid; e < 32 * 32; e += 256) {
            int i = e >> 5, j = e & 31;
            s[a][i][j] =
                src[((size_t)((b * AGENTS + a) * CH + c0 + i)) * HW + px0 + j];
        }
    }
    __syncthreads();

    for (int e = tid; e < 32 * 32; e += 256) {
        int i = e & 31;
        int j = e >> 5;
        int px = px0 + j;
        int py = (px >> 5) + 1, qx = (px & 31) + 1;
        float sum = 0.f;
#pragma unroll
        for (int a = 0; a < AGENTS; ++a) sum += s[a][i][j];
#pragma unroll
        for (int a = 0; a < AGENTS; ++a) {
            float own = s[a][i][j];
            float msg = (sum - own) * (1.0f / (AGENTS - 1));
            size_t base = ((size_t)((b * AGENTS + a) * PP + py) * PP + qx) * PCH;
            g_P[base + c0 + i] = __float2half(own);
            g_P[base + CH + c0 + i] = __float2half(msg);
        }
    }
}

// ---------------- mma.sync conv body ----------------------------------------
// CTA: 64 oc x 128 px, 128 threads (4 warps as 2m x 2n).
// K loop: (ci 32-chunks) x 9 taps, fp16x2 weight split (wh*x + wl*x).
// A tile: 64 rows x 128B [wh 64B | wl 64B], phys chunk = c ^ (r&7).
// B tile: 128 px x 64B, phys 16B-chunk = c ^ ((px>>1)&3).
// Stage = 8KB A + 8KB B = 16KB; THREE stages (dist 2, cp_wait<1>); 4 CTAs/SM.
#define ABYTES 8192
#define STAGEB 16384
#define SMEMB (3 * STAGEB)          // 49152

template <int CI>
__device__ __forceinline__ void conv_body(
    uint32_t sb, const __half* __restrict__ Wh, const __half* __restrict__ Wl,
    const float* __restrict__ bias, float* __restrict__ outb, int ocb) {
    const int tid = threadIdx.x;
    const int lane = tid & 31;
    const int wid = tid >> 5;
    const int wm = wid >> 1;           // 0..1 -> 32-oc slice
    const int wn = wid & 1;            // 0..1 -> 64-px slice
    const int gid = lane >> 2;
    const int tig = lane & 3;

    const int y0 = blockIdx.x * 4;     // image row base
    const int img = blockIdx.z;

    constexpr int S = (CI / 32) * 9;   // 144 or 72 (divisible by 3)
    constexpr int ACI = COUT * CI;     // offA step per tap (elements)

    // ---- A copy precompute (4 x cp16/thread): rows rw0/rw1, chunk cch
    const int rw0 = tid >> 2, rw1 = rw0 + 32;     // 0..31, 32..63
    const int cch = tid & 3;
    const int c16e = cch * 8;
    const uint32_t dA0 = (uint32_t)rw0 * 128 + (uint32_t)((cch ^ (rw0 & 7)) << 4);
    const uint32_t dA1 = (uint32_t)rw1 * 128 + (uint32_t)((cch ^ (rw1 & 7)) << 4);
    const int aof0 = (ocb * 64 + rw0) * CI + c16e;
    const int aof1 = (ocb * 64 + rw1) * CI + c16e;

    // ---- B copy precompute (4 x cp16/thread): px row bp = tid
    const int bp = tid;
    const int bg = (bp >> 1) & 3;
    const int bofB = ((img * PP + y0 + (bp >> 5)) * PP + (bp & 31)) * PCH;
    uint32_t dB[4];
#pragma unroll
    for (int c = 0; c < 4; ++c)
        dB[c] = (uint32_t)(ABYTES + bp * 64 + ((c ^ bg) << 4));

    // ---- ldsm per-lane base offsets
    const int lr = lane & 15, lr7 = lr & 7, hb = lane >> 4;
    const uint32_t aoff0 = (uint32_t)((wm * 32 + lr) * 128) +
                           (uint32_t)((hb ^ lr7) << 4);
    const int g0 = (lr >> 1) & 3;
    const uint32_t boff0 = (uint32_t)(ABYTES + (wn * 64 + lr) * 64) +
                           (uint32_t)(((hb ^ (g0 & 1)) << 4) |
                                      (((g0 >> 1) & 1) << 5));

    // ---- incremental stage counters
    int tap_n = 0, kx_n = 0, chunkb = 0, offA = 0, offB = 0;
    auto issue = [&](uint32_t bb) {
        cp16(bb + dA0, Wh + aof0 + offA);
        cp16(bb + (dA0 ^ 64), Wl + aof0 + offA);
        cp16(bb + dA1, Wh + aof1 + offA);
        cp16(bb + (dA1 ^ 64), Wl + aof1 + offA);
#pragma unroll
        for (int c = 0; c < 4; ++c)
            cp16(bb + dB[c], g_P + bofB + offB + c * 8);
        CP_COMMIT();
        if (++tap_n == 9) {
            tap_n = 0; kx_n = 0; chunkb += 32; offA = chunkb; offB = chunkb;
        } else {
            offA += ACI;
            if (++kx_n == 3) { kx_n = 0; offB += (PP - 2) * PCH; }
            else offB += PCH;
        }
    };

    float d[2][8][4];
#pragma unroll
    for (int mi = 0; mi < 2; ++mi)
#pragma unroll
        for (int ni = 0; ni < 8; ++ni)
#pragma unroll
            for (int k = 0; k < 4; ++k) d[mi][ni][k] = 0.f;

    auto compute = [&](uint32_t base) {
#pragma unroll
        for (int ks = 0; ks < 2; ++ks) {
            const uint32_t kxx = ks ? 32u : 0u;
            uint32_t ah[2][4], al[2][4];
#pragma unroll
            for (int mi = 0; mi < 2; ++mi) {
                uint32_t aaddr = base + ((aoff0 + mi * 2048) ^ kxx);
                ldsm4(ah[mi][0], ah[mi][1], ah[mi][2], ah[mi][3], aaddr);
                ldsm4(al[mi][0], al[mi][1], al[mi][2], al[mi][3], aaddr ^ 64);
            }
            uint32_t bb[8][2];
#pragma unroll
            for (int nj = 0; nj < 4; ++nj) {
                uint32_t r0, r1, r2, r3;
                ldsm4(r0, r1, r2, r3, base + ((boff0 + nj * 1024) ^ kxx));
                bb[nj * 2][0] = r0; bb[nj * 2][1] = r2;
                bb[nj * 2 + 1][0] = r1; bb[nj * 2 + 1][1] = r3;
            }
#pragma unroll
            for (int mi = 0; mi < 2; ++mi)
#pragma unroll
                for (int ni = 0; ni < 8; ++ni) mma_fp16(d[mi][ni], ah[mi], bb[ni]);
#pragma unroll
            for (int mi = 0; mi < 2; ++mi)
#pragma unroll
                for (int ni = 0; ni < 8; ++ni) mma_fp16(d[mi][ni], al[mi], bb[ni]);
        }
    };

    const uint32_t b0 = sb, b1 = sb + STAGEB, b2 = sb + 2 * STAGEB;
    issue(b0);                          // stage 0
    issue(b1);                          // stage 1
    int s = 0;
    for (; s + 3 < S; s += 3) {
        cp_wait<1>(); __syncthreads();  // stage s visible
        issue(b2);                      // stage s+2
        compute(b0);                    // stage s
        cp_wait<1>(); __syncthreads();
        issue(b0);                      // stage s+3
        compute(b1);                    // stage s+1
        cp_wait<1>(); __syncthreads();
        issue(b1);                      // stage s+4
        compute(b2);                    // stage s+2
    }
    // tail: stages S-3, S-2, S-1 (S divisible by 3)
    cp_wait<1>(); __syncthreads();
    issue(b2);                          // stage S-1
    compute(b0);                        // stage S-3
    cp_wait<1>(); __syncthreads();
    compute(b1);                        // stage S-2
    cp_wait<0>(); __syncthreads();
    compute(b2);                        // stage S-1

    // ---- epilogue: fragment -> NCHW + bias
#pragma unroll
    for (int mi = 0; mi < 2; ++mi) {
        int oc_lo = ocb * 64 + wm * 32 + mi * 16 + gid;
        int oc_hi = oc_lo + 8;
        float bz0 = bias[oc_lo];
        float bz1 = bias[oc_hi];
        float* p0 = outb + ((size_t)img * COUT + oc_lo) * HW;
        float* p1 = outb + ((size_t)img * COUT + oc_hi) * HW;
#pragma unroll
        for (int ni = 0; ni < 8; ++ni) {
            int pix = y0 * 32 + wn * 64 + ni * 8 + tig * 2;
            float2 v0 = make_float2(d[mi][ni][0] + bz0, d[mi][ni][1] + bz0);
            float2 v1 = make_float2(d[mi][ni][2] + bz1, d[mi][ni][3] + bz1);
            *(float2*)(p0 + pix) = v0;
            *(float2*)(p1 + pix) = v1;
        }
    }
}

// merged conv: blockIdx.y<12 -> w_ih conv (CI=512) into g_gi,
//              else           -> w_hh conv (CI=256) into g_gh.
__global__ void __launch_bounds__(128, 4)
conv_both_kernel(const float* __restrict__ b_ih, const float* __restrict__ b_hh) {
    extern __shared__ char smc[];
    const uint32_t sb = smem_u32(smc);
    const int yq = blockIdx.y;
    if (yq < 12)
        conv_body<CIN1>(sb, g_wih_hi, g_wih_lo, b_ih, g_gi, yq);
    else
        conv_body<CH>(sb, g_whh_hi, g_whh_lo, b_hh, g_gh, yq - 12);
}

// ---------------- GRU elementwise ------------------------------------------
__device__ __forceinline__ float sigmoidf_(float x) { return 1.0f / (1.0f + expf(-x)); }
__device__ __forceinline__ float tanhf_(float x) {
    float e = expf(2.0f * x);
    return 1.0f - 2.0f / (e + 1.0f);
}

__global__ void gru_kernel(const float* __restrict__ hsrc, float* __restrict__ dst) {
    int idx = blockIdx.x * blockDim.x + threadIdx.x;   // 48*256*256
    int p4 = idx & 255;
    int c = (idx >> 8) & 255;
    int img = idx >> 16;
    if (img >= IMGS) return;

    const float4* gi4 = (const float4*)g_gi;
    const float4* gh4 = (const float4*)g_gh;

    size_t gbase = (size_t)img * COUT * 256;
    float4 ir = gi4[gbase + (size_t)c * 256 + p4];
    float4 ii = gi4[gbase + (size_t)(CH + c) * 256 + p4];
    float4 in_ = gi4[gbase + (size_t)(2 * CH + c) * 256 + p4];
    float4 hr = gh4[gbase + (size_t)c * 256 + p4];
    float4 hi = gh4[gbase + (size_t)(CH + c) * 256 + p4];
    float4 hn = gh4[gbase + (size_t)(2 * CH + c) * 256 + p4];
    float4 h = ((const float4*)hsrc)[(size_t)(img * CH + c) * 256 + p4];

    float4 o;
    {
        float r = sigmoidf_(ir.x + hr.x), z = sigmoidf_(ii.x + hi.x);
        float n = tanhf_(in_.x + r * hn.x);
        o.x = n + z * (h.x - n);
    }
    {
        float r = sigmoidf_(ir.y + hr.y), z = sigmoidf_(ii.y + hi.y);
        float n = tanhf_(in_.y + r * hn.y);
        o.y = n + z * (h.y - n);
    }
    {
        float r = sigmoidf_(ir.z + hr.z), z = sigmoidf_(ii.z + hi.z);
        float n = tanhf_(in_.z + r * hn.z);
        o.z = n + z * (h.z - n);
    }
    {
        float r = sigmoidf_(ir.w + hr.w), z = sigmoidf_(ii.w + hi.w);
        float n = tanhf_(in_.w + r * hn.w);
        o.w = n + z * (h.w - n);
    }
    ((float4*)dst)[(size_t)(img * CH + c) * 256 + p4] = o;
}

// ---------------- launch ----------------------------------------------------
extern "C" void kernel_launch(void* const* d_in, const int* in_sizes, int n_in,
                              void* d_out, int out_size) {
    const float* x = (const float*)d_in[0];
    const float* w_ih = (const float*)d_in[1];
    const float* w_hh = (const float*)d_in[2];
    const float* b_ih = (const float*)d_in[3];
    const float* b_hh = (const float*)d_in[4];
    float* out = (float*)d_out;

    cudaFuncSetAttribute(conv_both_kernel,
                         cudaFuncAttributeMaxDynamicSharedMemorySize, SMEMB);

    {
        int n = 9 * COUT * CIN1;
        wprep_kernel<<<(n + 255) / 256, 256>>>(w_ih, w_hh);
    }
    {
        int n = IMGS * PP * PP * 64;
        zero_border_kernel<<<(n + 255) / 256, 256>>>();
    }

    dim3 bgrid(32, 8, BATCH);                  // pxtile, ctile, b
    dim3 cgrid(8, 24, IMGS);                   // px-tiles, merged 64-oc tiles, imgs
    const int gru_blocks = (IMGS * CH * 256 + 255) / 256;

    for (int it = 0; it < NITER; ++it) {
        const float* src = (it == 0) ? x : out;
        build_nhwc_kernel<<<bgrid, 256>>>(src);
        conv_both_kernel<<<cgrid, 128, SMEMB>>>(b_ih, b_hh);
        gru_kernel<<<gru_blocks, 256>>>(src, out);
    }
}

// round 13
// speedup vs baseline: 1.1285x; 1.1285x over previous
#include <cuda_runtime.h>
#include <cuda_fp16.h>
#include <cstdint>

// ---------------- problem constants ---------------------------------------
#define BATCH 8
#define AGENTS 6
#define IMGS 48
#define CH 256
#define HH 32
#define WW 32
#define HW 1024
#define CIN1 512
#define COUT 768
#define NITER 3
#define PP 34            // padded H/W
#define PCH 512          // channels in padded NHWC activation array

// ---------------- device scratch (allocation is forbidden) ----------------
static __device__ __align__(16) __half g_P[(size_t)IMGS * PP * PP * PCH];
static __device__ __align__(16) __half g_wih_hi[(size_t)9 * COUT * CIN1];
static __device__ __align__(16) __half g_wih_lo[(size_t)9 * COUT * CIN1];
static __device__ __align__(16) __half g_whh_hi[(size_t)9 * COUT * CH];
static __device__ __align__(16) __half g_whh_lo[(size_t)9 * COUT * CH];
static __device__ __align__(16) float g_gi[(size_t)IMGS * COUT * HW];
static __device__ __align__(16) float g_gh[(size_t)IMGS * COUT * HW];

// ---------------- helpers ---------------------------------------------------
__device__ __forceinline__ uint32_t smem_u32(const void* p) {
    uint32_t a;
    asm("{ .reg .u64 t; cvta.to.shared.u64 t, %1; cvt.u32.u64 %0, t; }"
        : "=r"(a) : "l"(p));
    return a;
}
__device__ __forceinline__ void cp16(uint32_t smem, const void* g) {
    asm volatile("cp.async.cg.shared.global [%0], [%1], 16;"
                 :: "r"(smem), "l"(g));
}
#define CP_COMMIT() asm volatile("cp.async.commit_group;" ::: "memory")
template <int N>
__device__ __forceinline__ void cp_wait() {
    asm volatile("cp.async.wait_group %0;" :: "n"(N) : "memory");
}
__device__ __forceinline__ void ldsm4(uint32_t& r0, uint32_t& r1, uint32_t& r2,
                                      uint32_t& r3, uint32_t addr) {
    asm volatile("ldmatrix.sync.aligned.m8n8.x4.shared.b16 {%0,%1,%2,%3}, [%4];"
                 : "=r"(r0), "=r"(r1), "=r"(r2), "=r"(r3) : "r"(addr));
}
__device__ __forceinline__ void mma_fp16(float* d, const uint32_t* a,
                                         const uint32_t* b) {
    asm volatile(
        "mma.sync.aligned.m16n8k16.row.col.f32.f16.f16.f32 "
        "{%0,%1,%2,%3},{%4,%5,%6,%7},{%8,%9},{%0,%1,%2,%3};"
        : "+f"(d[0]), "+f"(d[1]), "+f"(d[2]), "+f"(d[3])
        : "r"(a[0]), "r"(a[1]), "r"(a[2]), "r"(a[3]), "r"(b[0]), "r"(b[1]));
}

// ---------------- prep: weight split/transpose to [tap][oc][ci] ------------
__global__ void wprep_kernel(const float* __restrict__ w_ih,
                             const float* __restrict__ w_hh) {
    int idx = blockIdx.x * blockDim.x + threadIdx.x;
    const int n1 = 9 * COUT * CIN1;
    if (idx < n1) {
        int t = idx / (COUT * CIN1);
        int rem = idx - t * (COUT * CIN1);
        int oc = rem / CIN1;
        int ci = rem - oc * CIN1;
        float v = w_ih[((size_t)oc * CIN1 + ci) * 9 + t];
        __half h = __float2half(v);
        g_wih_hi[idx] = h;
        g_wih_lo[idx] = __float2half(v - __half2float(h));
    }
    const int n2 = 9 * COUT * CH;
    if (idx < n2) {
        int t = idx / (COUT * CH);
        int rem = idx - t * (COUT * CH);
        int oc = rem / CH;
        int ci = rem - oc * CH;
        float v = w_hh[((size_t)oc * CH + ci) * 9 + t];
        __half h = __float2half(v);
        g_whh_hi[idx] = h;
        g_whh_lo[idx] = __float2half(v - __half2float(h));
    }
}

// ---------------- zero padded borders --------------------------------------
__global__ void zero_border_kernel() {
    int idx = blockIdx.x * blockDim.x + threadIdx.x;   // img*1156*64
    int g = idx & 63;
    int pix = (idx >> 6) % (PP * PP);
    int img = idx / (64 * PP * PP);
    if (img >= IMGS) return;
    int pp = pix / PP, qq = pix % PP;
    if (pp != 0 && pp != PP - 1 && qq != 0 && qq != PP - 1) return;
    size_t off = ((size_t)(img * PP * PP) + pix) * PCH + g * 8;
    float4 z = make_float4(0.f, 0.f, 0.f, 0.f);
    *(float4*)&g_P[off] = z;
}

// ---------------- build padded NHWC fp16 from NCHW fp32 --------------------
__global__ void build_nhwc_kernel(const float* __restrict__ src) {
    __shared__ float s[AGENTS][32][33];
    const int tid = threadIdx.x;
    const int px0 = blockIdx.x * 32;
    const int c0 = blockIdx.y * 32;
    const int b = blockIdx.z;

#pragma unroll
    for (int a = 0; a < AGENTS; ++a) {
        for (int e = tid; e < 32 * 32; e += 256) {
            int i = e >> 5, j = e & 31;
            s[a][i][j] =
                src[((size_t)((b * AGENTS + a) * CH + c0 + i)) * HW + px0 + j];
        }
    }
    __syncthreads();

    for (int e = tid; e < 32 * 32; e += 256) {
        int i = e & 31;
        int j = e >> 5;
        int px = px0 + j;
        int py = (px >> 5) + 1, qx = (px & 31) + 1;
        float sum = 0.f;
#pragma unroll
        for (int a = 0; a < AGENTS; ++a) sum += s[a][i][j];
#pragma unroll
        for (int a = 0; a < AGENTS; ++a) {
            float own = s[a][i][j];
            float msg = (sum - own) * (1.0f / (AGENTS - 1));
            size_t base = ((size_t)((b * AGENTS + a) * PP + py) * PP + qx) * PCH;
            g_P[base + c0 + i] = __float2half(own);
            g_P[base + CH + c0 + i] = __float2half(msg);
        }
    }
}

// ---------------- mma.sync conv body ----------------------------------------
// CTA: 128 oc x 128 px, 256 threads (8 warps as 4m x 2n)   [R11 config]
// K loop: (ci 32-chunks) x 9 taps, fp16x2 weight split (wh*x + wl*x).
// A tile (per tap): 128 rows x 128B [wh|wl], phys chunk = c ^ (row&7);
//   A ring: 4 stages, prefetch distance 3 (cp_wait<2>).
// B tile (per ci-CHUNK, shared by all 9 taps): [6 rows][36 q][32 ci],
//   row rr = rt*36+q at rr*64B, 16B-chunk phys = c ^ ((rr>>1)&3); 2-deep ring.
//   Tap (ky,kx) reads row rr = rb + ky*36 + kx  (uniform addend).
#define ABUF 16384
#define ARING (4 * ABUF)                 // 65536
#define BSTRIDE 14336                    // 6*36*64 = 13824, padded
#define SMEMB (ARING + 2 * BSTRIDE)      // 94208

template <int CI>
__device__ __forceinline__ void conv_body(
    uint32_t sb, const __half* __restrict__ Wh, const __half* __restrict__ Wl,
    const float* __restrict__ bias, float* __restrict__ outb, int ocb) {
    const int tid = threadIdx.x;
    const int lane = tid & 31;
    const int wid = tid >> 5;
    const int wm = wid >> 1;           // 0..3 -> 32-oc slice
    const int wn = wid & 1;            // 0..1 -> 64-px slice
    const int gid = lane >> 2;
    const int tig = lane & 3;

    const int y0 = blockIdx.x * 4;     // image row base
    const int img = blockIdx.z;

    constexpr int S = (CI / 32) * 9;   // 144 or 72 (divisible by 4)
    constexpr int ACI = COUT * CI;     // offA step per tap (elements)

    // ---- A copy precompute (4 x cp16/thread)  [identical to R11]
    const int rw0 = tid >> 2, rw1 = rw0 + 64;
    const int cch = tid & 3;
    const int c16e = cch * 8;
    const uint32_t dA0 = (uint32_t)rw0 * 128 + (uint32_t)((cch ^ (rw0 & 7)) << 4);
    const uint32_t dA1 = (uint32_t)rw1 * 128 + (uint32_t)((cch ^ (rw1 & 7)) << 4);
    const int aof0 = (ocb * 128 + rw0) * CI + c16e;
    const int aof1 = (ocb * 128 + rw1) * CI + c16e;

    // ---- B copy precompute: thread t<204 copies row (rt,q), 4 x cp16 = 64B
    const bool tB = tid < 204;
    const int rt = tid / 34;
    const int q = tid - rt * 34;
    const int rrW = rt * 36 + q;
    uint32_t dBW[4];
#pragma unroll
    for (int c = 0; c < 4; ++c)
        dBW[c] = (uint32_t)((rrW << 6) + ((c ^ ((rrW >> 1) & 3)) << 4));
    const int bofP = ((img * PP + y0 + rt) * PP + q) * PCH;
    const uint32_t Bring = sb + ARING;

    // ---- ldsm per-lane base offsets
    const int lr = lane & 15, lr7 = lr & 7, hb = lane >> 4;
    const uint32_t aoff0 = (uint32_t)((wm * 32 + lr) * 128) +
                           (uint32_t)((hb ^ lr7) << 4);
    int rb[4];
#pragma unroll
    for (int nj = 0; nj < 4; ++nj) {
        int px = wn * 64 + nj * 16 + lr;
        rb[nj] = (px >> 5) * 36 + (px & 31);
    }

    // ---- issue-side counters
    int tap_n = 0, ichunk = 0, offA = 0;
    auto issue = [&](uint32_t abuf) {
        cp16(abuf + dA0, Wh + aof0 + offA);
        cp16(abuf + (dA0 ^ 64), Wl + aof0 + offA);
        cp16(abuf + dA1, Wh + aof1 + offA);
        cp16(abuf + (dA1 ^ 64), Wl + aof1 + offA);
        if (tap_n == 0 && tB) {
            uint32_t bb = Bring + (uint32_t)(ichunk & 1) * BSTRIDE;
            const __half* srcp = g_P + bofP + (ichunk << 5);
#pragma unroll
            for (int c = 0; c < 4; ++c)
                cp16(bb + dBW[c], srcp + c * 8);
        }
        CP_COMMIT();
        if (++tap_n == 9) { tap_n = 0; ++ichunk; offA = ichunk << 5; }
        else offA += ACI;
    };

    float d[2][8][4];
#pragma unroll
    for (int mi = 0; mi < 2; ++mi)
#pragma unroll
        for (int ni = 0; ni < 8; ++ni)
#pragma unroll
            for (int k = 0; k < 4; ++k) d[mi][ni][k] = 0.f;

    // ---- compute-side counters
    int ctap = 0, ckx = 0, ctapoff = 0;
    uint32_t cBb = Bring;              // current chunk's B buffer
    auto compute = [&](uint32_t abase) {
#pragma unroll
        for (int ks = 0; ks < 2; ++ks) {
            const uint32_t kxx = ks ? 32u : 0u;
            const uint32_t lc = (uint32_t)(hb + 2 * ks);   // logical 16B chunk
            uint32_t ah[2][4], al[2][4];
#pragma unroll
            for (int mi = 0; mi < 2; ++mi) {
                uint32_t aaddr = abase + ((aoff0 + mi * 2048) ^ kxx);
                ldsm4(ah[mi][0], ah[mi][1], ah[mi][2], ah[mi][3], aaddr);
                ldsm4(al[mi][0], al[mi][1], al[mi][2], al[mi][3], aaddr ^ 64);
            }
            uint32_t bb[8][2];
#pragma unroll
            for (int nj = 0; nj < 4; ++nj) {
                int rr = rb[nj] + ctapoff;
                uint32_t baddr = cBb + ((uint32_t)rr << 6) +
                                 ((lc ^ ((uint32_t)(rr >> 1) & 3)) << 4);
                uint32_t r0, r1, r2, r3;
                ldsm4(r0, r1, r2, r3, baddr);
                bb[nj * 2][0] = r0; bb[nj * 2][1] = r2;
                bb[nj * 2 + 1][0] = r1; bb[nj * 2 + 1][1] = r3;
            }
#pragma unroll
            for (int mi = 0; mi < 2; ++mi)
#pragma unroll
                for (int ni = 0; ni < 8; ++ni) mma_fp16(d[mi][ni], ah[mi], bb[ni]);
#pragma unroll
            for (int mi = 0; mi < 2; ++mi)
#pragma unroll
                for (int ni = 0; ni < 8; ++ni) mma_fp16(d[mi][ni], al[mi], bb[ni]);
        }
        // advance compute-side tap/chunk state
        if (++ctap == 9) {
            ctap = 0; ckx = 0; ctapoff = 0; cBb ^= BSTRIDE;
        } else {
            if (++ckx == 3) { ckx = 0; ctapoff += 34; }
            else ++ctapoff;
        }
    };

    const uint32_t b0 = sb, b1 = sb + ABUF, b2 = sb + 2 * ABUF,
                   b3 = sb + 3 * ABUF;
    issue(b0); issue(b1); issue(b2);
    int s = 0;
    for (; s + 8 <= S; s += 4) {
        cp_wait<2>(); __syncthreads(); issue(b3); compute(b0);
        cp_wait<2>(); __syncthreads(); issue(b0); compute(b1);
        cp_wait<2>(); __syncthreads(); issue(b1); compute(b2);
        cp_wait<2>(); __syncthreads(); issue(b2); compute(b3);
    }
    // tail: s == S-4
    cp_wait<2>(); __syncthreads(); issue(b3); compute(b0);   // stage S-4
    cp_wait<2>(); __syncthreads(); compute(b1);              // stage S-3
    cp_wait<1>(); __syncthreads(); compute(b2);              // stage S-2
    cp_wait<0>(); __syncthreads(); compute(b3);              // stage S-1

    // ---- epilogue: fragment -> NCHW + bias
#pragma unroll
    for (int mi = 0; mi < 2; ++mi) {
        int oc_lo = ocb * 128 + wm * 32 + mi * 16 + gid;
        int oc_hi = oc_lo + 8;
        float bz0 = bias[oc_lo];
        float bz1 = bias[oc_hi];
        float* p0 = outb + ((size_t)img * COUT + oc_lo) * HW;
        float* p1 = outb + ((size_t)img * COUT + oc_hi) * HW;
#pragma unroll
        for (int ni = 0; ni < 8; ++ni) {
            int pix = y0 * 32 + wn * 64 + ni * 8 + tig * 2;
            float2 v0 = make_float2(d[mi][ni][0] + bz0, d[mi][ni][1] + bz0);
            float2 v1 = make_float2(d[mi][ni][2] + bz1, d[mi][ni][3] + bz1);
            *(float2*)(p0 + pix) = v0;
            *(float2*)(p1 + pix) = v1;
        }
    }
}

// merged conv: blockIdx.y<6 -> w_ih conv (CI=512) into g_gi,
//              else          -> w_hh conv (CI=256) into g_gh.
__global__ void __launch_bounds__(256, 2)
conv_both_kernel(const float* __restrict__ b_ih, const float* __restrict__ b_hh) {
    extern __shared__ char smc[];
    const uint32_t sb = smem_u32(smc);
    const int yq = blockIdx.y;
    if (yq < 6)
        conv_body<CIN1>(sb, g_wih_hi, g_wih_lo, b_ih, g_gi, yq);
    else
        conv_body<CH>(sb, g_whh_hi, g_whh_lo, b_hh, g_gh, yq - 6);
}

// ---------------- GRU elementwise ------------------------------------------
__device__ __forceinline__ float sigmoidf_(float x) { return 1.0f / (1.0f + expf(-x)); }
__device__ __forceinline__ float tanhf_(float x) {
    float e = expf(2.0f * x);
    return 1.0f - 2.0f / (e + 1.0f);
}

__global__ void gru_kernel(const float* __restrict__ hsrc, float* __restrict__ dst) {
    int idx = blockIdx.x * blockDim.x + threadIdx.x;   // 48*256*256
    int p4 = idx & 255;
    int c = (idx >> 8) & 255;
    int img = idx >> 16;
    if (img >= IMGS) return;

    const float4* gi4 = (const float4*)g_gi;
    const float4* gh4 = (const float4*)g_gh;

    size_t gbase = (size_t)img * COUT * 256;
    float4 ir = gi4[gbase + (size_t)c * 256 + p4];
    float4 ii = gi4[gbase + (size_t)(CH + c) * 256 + p4];
    float4 in_ = gi4[gbase + (size_t)(2 * CH + c) * 256 + p4];
    float4 hr = gh4[gbase + (size_t)c * 256 + p4];
    float4 hi = gh4[gbase + (size_t)(CH + c) * 256 + p4];
    float4 hn = gh4[gbase + (size_t)(2 * CH + c) * 256 + p4];
    float4 h = ((const float4*)hsrc)[(size_t)(img * CH + c) * 256 + p4];

    float4 o;
    {
        float r = sigmoidf_(ir.x + hr.x), z = sigmoidf_(ii.x + hi.x);
        float n = tanhf_(in_.x + r * hn.x);
        o.x = n + z * (h.x - n);
    }
    {
        float r = sigmoidf_(ir.y + hr.y), z = sigmoidf_(ii.y + hi.y);
        float n = tanhf_(in_.y + r * hn.y);
        o.y = n + z * (h.y - n);
    }
    {
        float r = sigmoidf_(ir.z + hr.z), z = sigmoidf_(ii.z + hi.z);
        float n = tanhf_(in_.z + r * hn.z);
        o.z = n + z * (h.z - n);
    }
    {
        float r = sigmoidf_(ir.w + hr.w), z = sigmoidf_(ii.w + hi.w);
        float n = tanhf_(in_.w + r * hn.w);
        o.w = n + z * (h.w - n);
    }
    ((float4*)dst)[(size_t)(img * CH + c) * 256 + p4] = o;
}

// ---------------- launch ----------------------------------------------------
extern "C" void kernel_launch(void* const* d_in, const int* in_sizes, int n_in,
                              void* d_out, int out_size) {
    const float* x = (const float*)d_in[0];
    const float* w_ih = (const float*)d_in[1];
    const float* w_hh = (const float*)d_in[2];
    const float* b_ih = (const float*)d_in[3];
    const float* b_hh = (const float*)d_in[4];
    float* out = (float*)d_out;

    cudaFuncSetAttribute(conv_both_kernel,
                         cudaFuncAttributeMaxDynamicSharedMemorySize, SMEMB);

    {
        int n = 9 * COUT * CIN1;
        wprep_kernel<<<(n + 255) / 256, 256>>>(w_ih, w_hh);
    }
    {
        int n = IMGS * PP * PP * 64;
        zero_border_kernel<<<(n + 255) / 256, 256>>>();
    }

    dim3 bgrid(32, 8, BATCH);                  // pxtile, ctile, b
    dim3 cgrid(8, 12, IMGS);                   // px-tiles, merged oc-tiles, imgs
    const int gru_blocks = (IMGS * CH * 256 + 255) / 256;

    for (int it = 0; it < NITER; ++it) {
        const float* src = (it == 0) ? x : out;
        build_nhwc_kernel<<<bgrid, 256>>>(src);
        conv_both_kernel<<<cgrid, 256, SMEMB>>>(b_ih, b_hh);
        gru_kernel<<<gru_blocks, 256>>>(src, out);
    }
}

// round 14
// speedup vs baseline: 1.9001x; 1.6838x over previous
#include <cuda_runtime.h>
#include <cuda_fp16.h>
#include <cstdint>

// ---------------- problem constants ---------------------------------------
#define BATCH 8
#define AGENTS 6
#define IMGS 48
#define CH 256
#define HH 32
#define WW 32
#define HW 1024
#define CIN1 512
#define COUT 768
#define NITER 3
#define PP 34            // padded H/W
#define PCH 512          // channels in padded NHWC activation array

// ---------------- device scratch (allocation is forbidden) ----------------
static __device__ __align__(16) __half g_P[(size_t)IMGS * PP * PP * PCH];
static __device__ __align__(16) __half g_wih[(size_t)9 * COUT * CIN1];
static __device__ __align__(16) __half g_whh[(size_t)9 * COUT * CH];
static __device__ __align__(16) float g_gi[(size_t)IMGS * COUT * HW];
static __device__ __align__(16) float g_gh[(size_t)IMGS * COUT * HW];

// ---------------- helpers ---------------------------------------------------
__device__ __forceinline__ uint32_t smem_u32(const void* p) {
    uint32_t a;
    asm("{ .reg .u64 t; cvta.to.shared.u64 t, %1; cvt.u32.u64 %0, t; }"
        : "=r"(a) : "l"(p));
    return a;
}
__device__ __forceinline__ void cp16(uint32_t smem, const void* g) {
    asm volatile("cp.async.cg.shared.global [%0], [%1], 16;"
                 :: "r"(smem), "l"(g));
}
#define CP_COMMIT() asm volatile("cp.async.commit_group;" ::: "memory")
template <int N>
__device__ __forceinline__ void cp_wait() {
    asm volatile("cp.async.wait_group %0;" :: "n"(N) : "memory");
}
__device__ __forceinline__ void ldsm4(uint32_t& r0, uint32_t& r1, uint32_t& r2,
                                      uint32_t& r3, uint32_t addr) {
    asm volatile("ldmatrix.sync.aligned.m8n8.x4.shared.b16 {%0,%1,%2,%3}, [%4];"
                 : "=r"(r0), "=r"(r1), "=r"(r2), "=r"(r3) : "r"(addr));
}
__device__ __forceinline__ void mma_fp16(float* d, const uint32_t* a,
                                         const uint32_t* b) {
    asm volatile(
        "mma.sync.aligned.m16n8k16.row.col.f32.f16.f16.f32 "
        "{%0,%1,%2,%3},{%4,%5,%6,%7},{%8,%9},{%0,%1,%2,%3};"
        : "+f"(d[0]), "+f"(d[1]), "+f"(d[2]), "+f"(d[3])
        : "r"(a[0]), "r"(a[1]), "r"(a[2]), "r"(a[3]), "r"(b[0]), "r"(b[1]));
}

// ---------------- prep: weight round/transpose to [tap][oc][ci] ------------
__global__ void wprep_kernel(const float* __restrict__ w_ih,
                             const float* __restrict__ w_hh) {
    int idx = blockIdx.x * blockDim.x + threadIdx.x;
    const int n1 = 9 * COUT * CIN1;
    if (idx < n1) {
        int t = idx / (COUT * CIN1);
        int rem = idx - t * (COUT * CIN1);
        int oc = rem / CIN1;
        int ci = rem - oc * CIN1;
        g_wih[idx] = __float2half(w_ih[((size_t)oc * CIN1 + ci) * 9 + t]);
    }
    const int n2 = 9 * COUT * CH;
    if (idx < n2) {
        int t = idx / (COUT * CH);
        int rem = idx - t * (COUT * CH);
        int oc = rem / CH;
        int ci = rem - oc * CH;
        g_whh[idx] = __float2half(w_hh[((size_t)oc * CH + ci) * 9 + t]);
    }
}

// ---------------- zero padded borders --------------------------------------
__global__ void zero_border_kernel() {
    int idx = blockIdx.x * blockDim.x + threadIdx.x;   // img*1156*64
    int g = idx & 63;
    int pix = (idx >> 6) % (PP * PP);
    int img = idx / (64 * PP * PP);
    if (img >= IMGS) return;
    int pp = pix / PP, qq = pix % PP;
    if (pp != 0 && pp != PP - 1 && qq != 0 && qq != PP - 1) return;
    size_t off = ((size_t)(img * PP * PP) + pix) * PCH + g * 8;
    float4 z = make_float4(0.f, 0.f, 0.f, 0.f);
    *(float4*)&g_P[off] = z;
}

// ---------------- build padded NHWC fp16 from NCHW fp32 --------------------
__global__ void build_nhwc_kernel(const float* __restrict__ src) {
    __shared__ float s[AGENTS][32][33];
    const int tid = threadIdx.x;
    const int px0 = blockIdx.x * 32;
    const int c0 = blockIdx.y * 32;
    const int b = blockIdx.z;

#pragma unroll
    for (int a = 0; a < AGENTS; ++a) {
        for (int e = tid; e < 32 * 32; e += 256) {
            int i = e >> 5, j = e & 31;
            s[a][i][j] =
                src[((size_t)((b * AGENTS + a) * CH + c0 + i)) * HW + px0 + j];
        }
    }
    __syncthreads();

    for (int e = tid; e < 32 * 32; e += 256) {
        int i = e & 31;
        int j = e >> 5;
        int px = px0 + j;
        int py = (px >> 5) + 1, qx = (px & 31) + 1;
        float sum = 0.f;
#pragma unroll
        for (int a = 0; a < AGENTS; ++a) sum += s[a][i][j];
#pragma unroll
        for (int a = 0; a < AGENTS; ++a) {
            float own = s[a][i][j];
            float msg = (sum - own) * (1.0f / (AGENTS - 1));
            size_t base = ((size_t)((b * AGENTS + a) * PP + py) * PP + qx) * PCH;
            g_P[base + c0 + i] = __float2half(own);
            g_P[base + CH + c0 + i] = __float2half(msg);
        }
    }
}

// ---------------- mma.sync conv body ----------------------------------------
// CTA: 128 oc x 128 px, 256 threads (8 warps as 4m x 2n).
// K loop: (ci 32-chunks) x 9 taps, SINGLE fp16 weight (no split).
// A tile: 128 rows x 64B, 16B-chunk phys = c ^ ((row>>1)&3).
// B tile: 128 px x 64B, same swizzle (validated R11).
// Stage = 8KB A + 8KB B = 16KB; FOUR stages (prefetch distance 3); 2 CTAs/SM.
#define ABYTES 8192
#define STAGEB 16384
#define SMEMB (4 * STAGEB)          // 65536

template <int CI>
__device__ __forceinline__ void conv_body(
    uint32_t sb, const __half* __restrict__ W,
    const float* __restrict__ bias, float* __restrict__ outb, int ocb) {
    const int tid = threadIdx.x;
    const int lane = tid & 31;
    const int wid = tid >> 5;
    const int wm = wid >> 1;           // 0..3 -> 32-oc slice
    const int wn = wid & 1;            // 0..1 -> 64-px slice
    const int gid = lane >> 2;
    const int tig = lane & 3;

    const int y0 = blockIdx.x * 4;     // image row base
    const int img = blockIdx.z;

    constexpr int S = (CI / 32) * 9;   // 144 or 72 (divisible by 4)
    constexpr int ACI = COUT * CI;     // offA step per tap (elements)

    // ---- A copy precompute (2 x cp16/thread): row rwA = tid>>1
    const int rwA = tid >> 1;
    const int cA = (tid & 1) * 2;                    // chunks cA, cA+1
    const int gA = (rwA >> 1) & 3;
    const uint32_t dA0 = (uint32_t)(rwA * 64 + (((cA + 0) ^ gA) << 4));
    const uint32_t dA1 = (uint32_t)(rwA * 64 + (((cA + 1) ^ gA) << 4));
    const int aofA = (ocb * 128 + rwA) * CI + cA * 8;

    // ---- B copy precompute (2 x cp16/thread): px p = tid>>1, half h = tid&1
    const int bp = tid >> 1, bh = tid & 1;
    const int bg = (bp >> 1) & 3;
    const int bofB = ((img * PP + y0 + (bp >> 5)) * PP + (bp & 31)) * PCH + bh * 16;
    const uint32_t dB0 = (uint32_t)(ABYTES + bp * 64 +
        ((((0 ^ (bg & 1)) << 4) | (((bh ^ (bg >> 1)) & 1) << 5))));
    const uint32_t dB1 = (uint32_t)(ABYTES + bp * 64 +
        ((((1 ^ (bg & 1)) << 4) | (((bh ^ (bg >> 1)) & 1) << 5))));

    // ---- ldsm per-lane base offsets (ks: ^32; mi: +1024; nj: +1024)
    const int lr = lane & 15, hb = lane >> 4;
    const int gL = (lr >> 1) & 3;
    const uint32_t aoff0 = (uint32_t)((wm * 32 + lr) * 64) +
                           (uint32_t)(((hb ^ (gL & 1)) << 4) |
                                      (((gL >> 1) & 1) << 5));
    const uint32_t boff0 = (uint32_t)(ABYTES + (wn * 64 + lr) * 64) +
                           (uint32_t)(((hb ^ (gL & 1)) << 4) |
                                      (((gL >> 1) & 1) << 5));

    // ---- incremental stage counters
    int tap_n = 0, kx_n = 0, chunkb = 0, offA = 0, offB = 0;
    auto issue = [&](uint32_t bb) {
        cp16(bb + dA0, W + aofA + offA);
        cp16(bb + dA1, W + aofA + offA + 8);
        cp16(bb + dB0, g_P + bofB + offB);
        cp16(bb + dB1, g_P + bofB + offB + 8);
        CP_COMMIT();
        if (++tap_n == 9) {
            tap_n = 0; kx_n = 0; chunkb += 32; offA = chunkb; offB = chunkb;
        } else {
            offA += ACI;
            if (++kx_n == 3) { kx_n = 0; offB += (PP - 2) * PCH; }
            else offB += PCH;
        }
    };

    float d[2][8][4];
#pragma unroll
    for (int mi = 0; mi < 2; ++mi)
#pragma unroll
        for (int ni = 0; ni < 8; ++ni)
#pragma unroll
            for (int k = 0; k < 4; ++k) d[mi][ni][k] = 0.f;

    auto compute = [&](uint32_t base) {
#pragma unroll
        for (int ks = 0; ks < 2; ++ks) {
            const uint32_t kxx = ks ? 32u : 0u;
            uint32_t ah[2][4];
#pragma unroll
            for (int mi = 0; mi < 2; ++mi) {
                uint32_t aaddr = base + ((aoff0 + mi * 1024) ^ kxx);
                ldsm4(ah[mi][0], ah[mi][1], ah[mi][2], ah[mi][3], aaddr);
            }
            uint32_t bb[8][2];
#pragma unroll
            for (int nj = 0; nj < 4; ++nj) {
                uint32_t r0, r1, r2, r3;
                ldsm4(r0, r1, r2, r3, base + ((boff0 + nj * 1024) ^ kxx));
                bb[nj * 2][0] = r0; bb[nj * 2][1] = r2;
                bb[nj * 2 + 1][0] = r1; bb[nj * 2 + 1][1] = r3;
            }
#pragma unroll
            for (int mi = 0; mi < 2; ++mi)
#pragma unroll
                for (int ni = 0; ni < 8; ++ni) mma_fp16(d[mi][ni], ah[mi], bb[ni]);
        }
    };

    const uint32_t b0 = sb, b1 = sb + STAGEB, b2 = sb + 2 * STAGEB,
                   b3 = sb + 3 * STAGEB;
    issue(b0); issue(b1); issue(b2);
    int s = 0;
    for (; s + 8 <= S; s += 4) {
        cp_wait<2>(); __syncthreads(); issue(b3); compute(b0);
        cp_wait<2>(); __syncthreads(); issue(b0); compute(b1);
        cp_wait<2>(); __syncthreads(); issue(b1); compute(b2);
        cp_wait<2>(); __syncthreads(); issue(b2); compute(b3);
    }
    // tail: s == S-4
    cp_wait<2>(); __syncthreads(); issue(b3); compute(b0);   // stage S-4
    cp_wait<2>(); __syncthreads(); compute(b1);              // stage S-3
    cp_wait<1>(); __syncthreads(); compute(b2);              // stage S-2
    cp_wait<0>(); __syncthreads(); compute(b3);              // stage S-1

    // ---- epilogue: fragment -> NCHW + bias
#pragma unroll
    for (int mi = 0; mi < 2; ++mi) {
        int oc_lo = ocb * 128 + wm * 32 + mi * 16 + gid;
        int oc_hi = oc_lo + 8;
        float bz0 = bias[oc_lo];
        float bz1 = bias[oc_hi];
        float* p0 = outb + ((size_t)img * COUT + oc_lo) * HW;
        float* p1 = outb + ((size_t)img * COUT + oc_hi) * HW;
#pragma unroll
        for (int ni = 0; ni < 8; ++ni) {
            int pix = y0 * 32 + wn * 64 + ni * 8 + tig * 2;
            float2 v0 = make_float2(d[mi][ni][0] + bz0, d[mi][ni][1] + bz0);
            float2 v1 = make_float2(d[mi][ni][2] + bz1, d[mi][ni][3] + bz1);
            *(float2*)(p0 + pix) = v0;
            *(float2*)(p1 + pix) = v1;
        }
    }
}

// merged conv: blockIdx.y<6 -> w_ih conv (CI=512) into g_gi,
//              else          -> w_hh conv (CI=256) into g_gh.
__global__ void __launch_bounds__(256, 2)
conv_both_kernel(const float* __restrict__ b_ih, const float* __restrict__ b_hh) {
    extern __shared__ char smc[];
    const uint32_t sb = smem_u32(smc);
    const int yq = blockIdx.y;
    if (yq < 6)
        conv_body<CIN1>(sb, g_wih, b_ih, g_gi, yq);
    else
        conv_body<CH>(sb, g_whh, b_hh, g_gh, yq - 6);
}

// ---------------- GRU elementwise ------------------------------------------
__device__ __forceinline__ float sigmoidf_(float x) { return 1.0f / (1.0f + expf(-x)); }
__device__ __forceinline__ float tanhf_(float x) {
    float e = expf(2.0f * x);
    return 1.0f - 2.0f / (e + 1.0f);
}

__global__ void gru_kernel(const float* __restrict__ hsrc, float* __restrict__ dst) {
    int idx = blockIdx.x * blockDim.x + threadIdx.x;   // 48*256*256
    int p4 = idx & 255;
    int c = (idx >> 8) & 255;
    int img = idx >> 16;
    if (img >= IMGS) return;

    const float4* gi4 = (const float4*)g_gi;
    const float4* gh4 = (const float4*)g_gh;

    size_t gbase = (size_t)img * COUT * 256;
    float4 ir = gi4[gbase + (size_t)c * 256 + p4];
    float4 ii = gi4[gbase + (size_t)(CH + c) * 256 + p4];
    float4 in_ = gi4[gbase + (size_t)(2 * CH + c) * 256 + p4];
    float4 hr = gh4[gbase + (size_t)c * 256 + p4];
    float4 hi = gh4[gbase + (size_t)(CH + c) * 256 + p4];
    float4 hn = gh4[gbase + (size_t)(2 * CH + c) * 256 + p4];
    float4 h = ((const float4*)hsrc)[(size_t)(img * CH + c) * 256 + p4];

    float4 o;
    {
        float r = sigmoidf_(ir.x + hr.x), z = sigmoidf_(ii.x + hi.x);
        float n = tanhf_(in_.x + r * hn.x);
        o.x = n + z * (h.x - n);
    }
    {
        float r = sigmoidf_(ir.y + hr.y), z = sigmoidf_(ii.y + hi.y);
        float n = tanhf_(in_.y + r * hn.y);
        o.y = n + z * (h.y - n);
    }
    {
        float r = sigmoidf_(ir.z + hr.z), z = sigmoidf_(ii.z + hi.z);
        float n = tanhf_(in_.z + r * hn.z);
        o.z = n + z * (h.z - n);
    }
    {
        float r = sigmoidf_(ir.w + hr.w), z = sigmoidf_(ii.w + hi.w);
        float n = tanhf_(in_.w + r * hn.w);
        o.w = n + z * (h.w - n);
    }
    ((float4*)dst)[(size_t)(img * CH + c) * 256 + p4] = o;
}

// ---------------- launch ----------------------------------------------------
extern "C" void kernel_launch(void* const* d_in, const int* in_sizes, int n_in,
                              void* d_out, int out_size) {
    const float* x = (const float*)d_in[0];
    const float* w_ih = (const float*)d_in[1];
    const float* w_hh = (const float*)d_in[2];
    const float* b_ih = (const float*)d_in[3];
    const float* b_hh = (const float*)d_in[4];
    float* out = (float*)d_out;

    cudaFuncSetAttribute(conv_both_kernel,
                         cudaFuncAttributeMaxDynamicSharedMemorySize, SMEMB);

    {
        int n = 9 * COUT * CIN1;
        wprep_kernel<<<(n + 255) / 256, 256>>>(w_ih, w_hh);
    }
    {
        int n = IMGS * PP * PP * 64;
        zero_border_kernel<<<(n + 255) / 256, 256>>>();
    }

    dim3 bgrid(32, 8, BATCH);                  // pxtile, ctile, b
    dim3 cgrid(8, 12, IMGS);                   // px-tiles, merged oc-tiles, imgs
    const int gru_blocks = (IMGS * CH * 256 + 255) / 256;

    for (int it = 0; it < NITER; ++it) {
        const float* src = (it == 0) ? x : out;
        build_nhwc_kernel<<<bgrid, 256>>>(src);
        conv_both_kernel<<<cgrid, 256, SMEMB>>>(b_ih, b_hh);
        gru_kernel<<<gru_blocks, 256>>>(src, out);
    }
}

// round 15
// speedup vs baseline: 2.5637x; 1.3493x over previous
#include <cuda_runtime.h>
#include <cuda_fp16.h>
#include <cstdint>

// ---------------- problem constants ---------------------------------------
#define BATCH 8
#define AGENTS 6
#define IMGS 48
#define CH 256
#define HH 32
#define WW 32
#define HW 1024
#define CIN1 512
#define COUT 768
#define NITER 3
#define PP 34            // padded H/W
#define PCH 512          // channels in padded NHWC activation array

// ---------------- device scratch (allocation is forbidden) ----------------
static __device__ __align__(16) __half g_P[(size_t)IMGS * PP * PP * PCH];
static __device__ __align__(16) __half g_wih[(size_t)9 * COUT * CIN1];
static __device__ __align__(16) __half g_whh[(size_t)9 * COUT * CH];
static __device__ __align__(16) float g_gi[(size_t)IMGS * COUT * HW];
static __device__ __align__(16) float g_gh[(size_t)IMGS * COUT * HW];

// ---------------- helpers ---------------------------------------------------
__device__ __forceinline__ uint32_t smem_u32(const void* p) {
    uint32_t a;
    asm("{ .reg .u64 t; cvta.to.shared.u64 t, %1; cvt.u32.u64 %0, t; }"
        : "=r"(a) : "l"(p));
    return a;
}
__device__ __forceinline__ void cp16(uint32_t smem, const void* g) {
    asm volatile("cp.async.cg.shared.global [%0], [%1], 16;"
                 :: "r"(smem), "l"(g));
}
#define CP_COMMIT() asm volatile("cp.async.commit_group;" ::: "memory")
template <int N>
__device__ __forceinline__ void cp_wait() {
    asm volatile("cp.async.wait_group %0;" :: "n"(N) : "memory");
}
__device__ __forceinline__ void ldsm4(uint32_t& r0, uint32_t& r1, uint32_t& r2,
                                      uint32_t& r3, uint32_t addr) {
    asm volatile("ldmatrix.sync.aligned.m8n8.x4.shared.b16 {%0,%1,%2,%3}, [%4];"
                 : "=r"(r0), "=r"(r1), "=r"(r2), "=r"(r3) : "r"(addr));
}
__device__ __forceinline__ void mma_fp16(float* d, const uint32_t* a,
                                         const uint32_t* b) {
    asm volatile(
        "mma.sync.aligned.m16n8k16.row.col.f32.f16.f16.f32 "
        "{%0,%1,%2,%3},{%4,%5,%6,%7},{%8,%9},{%0,%1,%2,%3};"
        : "+f"(d[0]), "+f"(d[1]), "+f"(d[2]), "+f"(d[3])
        : "r"(a[0]), "r"(a[1]), "r"(a[2]), "r"(a[3]), "r"(b[0]), "r"(b[1]));
}

// ---------------- prep: weight round/transpose to [tap][oc][ci] ------------
__global__ void wprep_kernel(const float* __restrict__ w_ih,
                             const float* __restrict__ w_hh) {
    int idx = blockIdx.x * blockDim.x + threadIdx.x;
    const int n1 = 9 * COUT * CIN1;
    if (idx < n1) {
        int t = idx / (COUT * CIN1);
        int rem = idx - t * (COUT * CIN1);
        int oc = rem / CIN1;
        int ci = rem - oc * CIN1;
        g_wih[idx] = __float2half(w_ih[((size_t)oc * CIN1 + ci) * 9 + t]);
    }
    const int n2 = 9 * COUT * CH;
    if (idx < n2) {
        int t = idx / (COUT * CH);
        int rem = idx - t * (COUT * CH);
        int oc = rem / CH;
        int ci = rem - oc * CH;
        g_whh[idx] = __float2half(w_hh[((size_t)oc * CH + ci) * 9 + t]);
    }
}

// ---------------- zero padded borders --------------------------------------
__global__ void zero_border_kernel() {
    int idx = blockIdx.x * blockDim.x + threadIdx.x;   // img*1156*64
    int g = idx & 63;
    int pix = (idx >> 6) % (PP * PP);
    int img = idx / (64 * PP * PP);
    if (img >= IMGS) return;
    int pp = pix / PP, qq = pix % PP;
    if (pp != 0 && pp != PP - 1 && qq != 0 && qq != PP - 1) return;
    size_t off = ((size_t)(img * PP * PP) + pix) * PCH + g * 8;
    float4 z = make_float4(0.f, 0.f, 0.f, 0.f);
    *(float4*)&g_P[off] = z;
}

// ---------------- build padded NHWC fp16 from NCHW fp32 --------------------
__global__ void build_nhwc_kernel(const float* __restrict__ src) {
    __shared__ float s[AGENTS][32][33];
    const int tid = threadIdx.x;
    const int px0 = blockIdx.x * 32;
    const int c0 = blockIdx.y * 32;
    const int b = blockIdx.z;

#pragma unroll
    for (int a = 0; a < AGENTS; ++a) {
        for (int e = tid; e < 32 * 32; e += 256) {
            int i = e >> 5, j = e & 31;
            s[a][i][j] =
                src[((size_t)((b * AGENTS + a) * CH + c0 + i)) * HW + px0 + j];
        }
    }
    __syncthreads();

    for (int e = tid; e < 32 * 32; e += 256) {
        int i = e & 31;
        int j = e >> 5;
        int px = px0 + j;
        int py = (px >> 5) + 1, qx = (px & 31) + 1;
        float sum = 0.f;
#pragma unroll
        for (int a = 0; a < AGENTS; ++a) sum += s[a][i][j];
#pragma unroll
        for (int a = 0; a < AGENTS; ++a) {
            float own = s[a][i][j];
            float msg = (sum - own) * (1.0f / (AGENTS - 1));
            size_t base = ((size_t)((b * AGENTS + a) * PP + py) * PP + qx) * PCH;
            g_P[base + c0 + i] = __float2half(own);
            g_P[base + CH + c0 + i] = __float2half(msg);
        }
    }
}

// ---------------- mma.sync conv body ----------------------------------------
// CTA: 128 oc x 128 px, 256 threads (8 warps as 4m x 2n).
// K loop: (ci 64-chunk-pairs) x 9 taps, single fp16 weights, K=64 per stage.
// A tile: 128 rows x 128B, 16B-chunk phys = c ^ (row&7)  [R10-validated SW128].
// B tile: 128 px x 128B, same swizzle.
// Stage = 16KB A + 16KB B = 32KB; THREE stages (dist 2, cp_wait<1>); 2 CTAs/SM.
#define ABYTES2 16384
#define STAGEB 32768
#define SMEMB (3 * STAGEB)          // 98304

template <int CI>
__device__ __forceinline__ void conv_body(
    uint32_t sb, const __half* __restrict__ W,
    const float* __restrict__ bias, float* __restrict__ outb, int ocb) {
    const int tid = threadIdx.x;
    const int lane = tid & 31;
    const int wid = tid >> 5;
    const int wm = wid >> 1;           // 0..3 -> 32-oc slice
    const int wn = wid & 1;            // 0..1 -> 64-px slice
    const int gid = lane >> 2;
    const int tig = lane & 3;

    const int y0 = blockIdx.x * 4;     // image row base
    const int img = blockIdx.z;

    constexpr int S = (CI / 64) * 9;   // 72 or 36 (divisible by 3)
    constexpr int ACI = COUT * CI;     // offA step per tap (elements)

    // ---- copy precompute: thread covers rows r0+32*it, chunk cA (constant)
    const int r0 = tid >> 3;                        // 0..31
    const int cA = tid & 7;
    const uint32_t sw = (uint32_t)((cA ^ (r0 & 7)) << 4);   // row&7 invariant
    const uint32_t dA = (uint32_t)r0 * 128 + sw;    // + it*4096
    const uint32_t dB = 16384u + dA;
    const int aofA = (ocb * 128 + r0) * CI + cA * 8;            // + it*32*CI
    const int bofB = ((img * PP + y0) * PP + r0) * PCH + cA * 8; // + it*PP*PCH

    // ---- ldsm per-lane base offsets (mi/nj: +2048, ks: ^(ks<<5))
    const int lr = lane & 15, hb = lane >> 4;
    const uint32_t aoff0 = (uint32_t)((wm * 32 + lr) * 128) +
                           (uint32_t)((hb ^ (lr & 7)) << 4);
    const uint32_t boff0 = 16384u + (uint32_t)((wn * 64 + lr) * 128) +
                           (uint32_t)((hb ^ (lr & 7)) << 4);

    // ---- incremental stage counters (tap inner, chunk-pair outer)
    int tap_n = 0, kx_n = 0, chunkb = 0, offA = 0, offB = 0;
    auto issue = [&](uint32_t bb) {
#pragma unroll
        for (int it = 0; it < 4; ++it) {
            cp16(bb + dA + it * 4096, W + aofA + it * 32 * CI + offA);
            cp16(bb + dB + it * 4096, g_P + bofB + it * PP * PCH + offB);
        }
        CP_COMMIT();
        if (++tap_n == 9) {
            tap_n = 0; kx_n = 0; chunkb += 64; offA = chunkb; offB = chunkb;
        } else {
            offA += ACI;
            if (++kx_n == 3) { kx_n = 0; offB += (PP - 2) * PCH; }
            else offB += PCH;
        }
    };

    float d[2][8][4];
#pragma unroll
    for (int mi = 0; mi < 2; ++mi)
#pragma unroll
        for (int ni = 0; ni < 8; ++ni)
#pragma unroll
            for (int k = 0; k < 4; ++k) d[mi][ni][k] = 0.f;

    auto compute = [&](uint32_t base) {
#pragma unroll
        for (int ks = 0; ks < 4; ++ks) {
            const uint32_t kxx = (uint32_t)ks << 5;
            uint32_t ah[2][4];
#pragma unroll
            for (int mi = 0; mi < 2; ++mi) {
                uint32_t aaddr = base + ((aoff0 + mi * 2048) ^ kxx);
                ldsm4(ah[mi][0], ah[mi][1], ah[mi][2], ah[mi][3], aaddr);
            }
            uint32_t bb[8][2];
#pragma unroll
            for (int nj = 0; nj < 4; ++nj) {
                uint32_t r0r, r1r, r2r, r3r;
                ldsm4(r0r, r1r, r2r, r3r, base + ((boff0 + nj * 2048) ^ kxx));
                bb[nj * 2][0] = r0r; bb[nj * 2][1] = r2r;
                bb[nj * 2 + 1][0] = r1r; bb[nj * 2 + 1][1] = r3r;
            }
#pragma unroll
            for (int mi = 0; mi < 2; ++mi)
#pragma unroll
                for (int ni = 0; ni < 8; ++ni) mma_fp16(d[mi][ni], ah[mi], bb[ni]);
        }
    };

    const uint32_t b0 = sb, b1 = sb + STAGEB, b2 = sb + 2 * STAGEB;
    issue(b0);                          // stage 0
    issue(b1);                          // stage 1
    int s = 0;
    for (; s + 3 < S; s += 3) {
        cp_wait<1>(); __syncthreads();  // stage s resident + slot free
        issue(b2);                      // stage s+2
        compute(b0);                    // stage s
        cp_wait<1>(); __syncthreads();
        issue(b0);                      // stage s+3
        compute(b1);                    // stage s+1
        cp_wait<1>(); __syncthreads();
        issue(b1);                      // stage s+4
        compute(b2);                    // stage s+2
    }
    // tail: stages S-3, S-2, S-1 (S divisible by 3)
    cp_wait<1>(); __syncthreads();
    issue(b2);                          // stage S-1
    compute(b0);                        // stage S-3
    cp_wait<1>(); __syncthreads();
    compute(b1);                        // stage S-2
    cp_wait<0>(); __syncthreads();
    compute(b2);                        // stage S-1

    // ---- epilogue: fragment -> NCHW + bias
#pragma unroll
    for (int mi = 0; mi < 2; ++mi) {
        int oc_lo = ocb * 128 + wm * 32 + mi * 16 + gid;
        int oc_hi = oc_lo + 8;
        float bz0 = bias[oc_lo];
        float bz1 = bias[oc_hi];
        float* p0 = outb + ((size_t)img * COUT + oc_lo) * HW;
        float* p1 = outb + ((size_t)img * COUT + oc_hi) * HW;
#pragma unroll
        for (int ni = 0; ni < 8; ++ni) {
            int pix = y0 * 32 + wn * 64 + ni * 8 + tig * 2;
            float2 v0 = make_float2(d[mi][ni][0] + bz0, d[mi][ni][1] + bz0);
            float2 v1 = make_float2(d[mi][ni][2] + bz1, d[mi][ni][3] + bz1);
            *(float2*)(p0 + pix) = v0;
            *(float2*)(p1 + pix) = v1;
        }
    }
}

// merged conv: blockIdx.y<6 -> w_ih conv (CI=512) into g_gi,
//              else          -> w_hh conv (CI=256) into g_gh.
__global__ void __launch_bounds__(256, 2)
conv_both_kernel(const float* __restrict__ b_ih, const float* __restrict__ b_hh) {
    extern __shared__ char smc[];
    const uint32_t sb = smem_u32(smc);
    const int yq = blockIdx.y;
    if (yq < 6)
        conv_body<CIN1>(sb, g_wih, b_ih, g_gi, yq);
    else
        conv_body<CH>(sb, g_whh, b_hh, g_gh, yq - 6);
}

// ---------------- GRU elementwise ------------------------------------------
__device__ __forceinline__ float sigmoidf_(float x) { return 1.0f / (1.0f + expf(-x)); }
__device__ __forceinline__ float tanhf_(float x) {
    float e = expf(2.0f * x);
    return 1.0f - 2.0f / (e + 1.0f);
}

__global__ void gru_kernel(const float* __restrict__ hsrc, float* __restrict__ dst) {
    int idx = blockIdx.x * blockDim.x + threadIdx.x;   // 48*256*256
    int p4 = idx & 255;
    int c = (idx >> 8) & 255;
    int img = idx >> 16;
    if (img >= IMGS) return;

    const float4* gi4 = (const float4*)g_gi;
    const float4* gh4 = (const float4*)g_gh;

    size_t gbase = (size_t)img * COUT * 256;
    float4 ir = gi4[gbase + (size_t)c * 256 + p4];
    float4 ii = gi4[gbase + (size_t)(CH + c) * 256 + p4];
    float4 in_ = gi4[gbase + (size_t)(2 * CH + c) * 256 + p4];
    float4 hr = gh4[gbase + (size_t)c * 256 + p4];
    float4 hi = gh4[gbase + (size_t)(CH + c) * 256 + p4];
    float4 hn = gh4[gbase + (size_t)(2 * CH + c) * 256 + p4];
    float4 h = ((const float4*)hsrc)[(size_t)(img * CH + c) * 256 + p4];

    float4 o;
    {
        float r = sigmoidf_(ir.x + hr.x), z = sigmoidf_(ii.x + hi.x);
        float n = tanhf_(in_.x + r * hn.x);
        o.x = n + z * (h.x - n);
    }
    {
        float r = sigmoidf_(ir.y + hr.y), z = sigmoidf_(ii.y + hi.y);
        float n = tanhf_(in_.y + r * hn.y);
        o.y = n + z * (h.y - n);
    }
    {
        float r = sigmoidf_(ir.z + hr.z), z = sigmoidf_(ii.z + hi.z);
        float n = tanhf_(in_.z + r * hn.z);
        o.z = n + z * (h.z - n);
    }
    {
        float r = sigmoidf_(ir.w + hr.w), z = sigmoidf_(ii.w + hi.w);
        float n = tanhf_(in_.w + r * hn.w);
        o.w = n + z * (h.w - n);
    }
    ((float4*)dst)[(size_t)(img * CH + c) * 256 + p4] = o;
}

// ---------------- launch ----------------------------------------------------
extern "C" void kernel_launch(void* const* d_in, const int* in_sizes, int n_in,
                              void* d_out, int out_size) {
    const float* x = (const float*)d_in[0];
    const float* w_ih = (const float*)d_in[1];
    const float* w_hh = (const float*)d_in[2];
    const float* b_ih = (const float*)d_in[3];
    const float* b_hh = (const float*)d_in[4];
    float* out = (float*)d_out;

    cudaFuncSetAttribute(conv_both_kernel,
                         cudaFuncAttributeMaxDynamicSharedMemorySize, SMEMB);

    {
        int n = 9 * COUT * CIN1;
        wprep_kernel<<<(n + 255) / 256, 256>>>(w_ih, w_hh);
    }
    {
        int n = IMGS * PP * PP * 64;
        zero_border_kernel<<<(n + 255) / 256, 256>>>();
    }

    dim3 bgrid(32, 8, BATCH);                  // pxtile, ctile, b
    dim3 cgrid(8, 12, IMGS);                   // px-tiles, merged oc-tiles, imgs
    const int gru_blocks = (IMGS * CH * 256 + 255) / 256;

    for (int it = 0; it < NITER; ++it) {
        const float* src = (it == 0) ? x : out;
        build_nhwc_kernel<<<bgrid, 256>>>(src);
        conv_both_kernel<<<cgrid, 256, SMEMB>>>(b_ih, b_hh);
        gru_kernel<<<gru_blocks, 256>>>(src, out);
    }
}

// round 16
// speedup vs baseline: 2.6369x; 1.0285x over previous
#include <cuda_runtime.h>
#include <cuda_fp16.h>
#include <cstdint>

// ---------------- problem constants ---------------------------------------
#define BATCH 8
#define AGENTS 6
#define IMGS 48
#define CH 256
#define HH 32
#define WW 32
#define HW 1024
#define CIN1 512
#define COUT 768
#define NITER 3
#define PP 34            // padded H/W
#define PCH 512          // channels in padded NHWC activation array

// ---------------- device scratch (allocation is forbidden) ----------------
static __device__ __align__(16) __half g_P[(size_t)IMGS * PP * PP * PCH];
static __device__ __align__(16) __half g_wih[(size_t)9 * COUT * CIN1];
static __device__ __align__(16) __half g_whh[(size_t)9 * COUT * CH];
static __device__ __align__(16) float g_gi[(size_t)IMGS * COUT * HW];
static __device__ __align__(16) float g_gh[(size_t)IMGS * COUT * HW];

// ---------------- helpers ---------------------------------------------------
__device__ __forceinline__ uint32_t smem_u32(const void* p) {
    uint32_t a;
    asm("{ .reg .u64 t; cvta.to.shared.u64 t, %1; cvt.u32.u64 %0, t; }"
        : "=r"(a) : "l"(p));
    return a;
}
__device__ __forceinline__ void cp16(uint32_t smem, const void* g) {
    asm volatile("cp.async.cg.shared.global [%0], [%1], 16;"
                 :: "r"(smem), "l"(g));
}
#define CP_COMMIT() asm volatile("cp.async.commit_group;" ::: "memory")
template <int N>
__device__ __forceinline__ void cp_wait() {
    asm volatile("cp.async.wait_group %0;" :: "n"(N) : "memory");
}
__device__ __forceinline__ void ldsm4(uint32_t& r0, uint32_t& r1, uint32_t& r2,
                                      uint32_t& r3, uint32_t addr) {
    asm volatile("ldmatrix.sync.aligned.m8n8.x4.shared.b16 {%0,%1,%2,%3}, [%4];"
                 : "=r"(r0), "=r"(r1), "=r"(r2), "=r"(r3) : "r"(addr));
}
__device__ __forceinline__ void mma_fp16(float* d, const uint32_t* a,
                                         const uint32_t* b) {
    asm volatile(
        "mma.sync.aligned.m16n8k16.row.col.f32.f16.f16.f32 "
        "{%0,%1,%2,%3},{%4,%5,%6,%7},{%8,%9},{%0,%1,%2,%3};"
        : "+f"(d[0]), "+f"(d[1]), "+f"(d[2]), "+f"(d[3])
        : "r"(a[0]), "r"(a[1]), "r"(a[2]), "r"(a[3]), "r"(b[0]), "r"(b[1]));
}

// ---------------- prep: weight round/transpose to [tap][oc][ci] ------------
__global__ void wprep_kernel(const float* __restrict__ w_ih,
                             const float* __restrict__ w_hh) {
    int idx = blockIdx.x * blockDim.x + threadIdx.x;
    const int n1 = 9 * COUT * CIN1;
    if (idx < n1) {
        int t = idx / (COUT * CIN1);
        int rem = idx - t * (COUT * CIN1);
        int oc = rem / CIN1;
        int ci = rem - oc * CIN1;
        g_wih[idx] = __float2half(w_ih[((size_t)oc * CIN1 + ci) * 9 + t]);
    }
    const int n2 = 9 * COUT * CH;
    if (idx < n2) {
        int t = idx / (COUT * CH);
        int rem = idx - t * (COUT * CH);
        int oc = rem / CH;
        int ci = rem - oc * CH;
        g_whh[idx] = __float2half(w_hh[((size_t)oc * CH + ci) * 9 + t]);
    }
}

// ---------------- zero padded borders --------------------------------------
__global__ void zero_border_kernel() {
    int idx = blockIdx.x * blockDim.x + threadIdx.x;   // img*1156*64
    int g = idx & 63;
    int pix = (idx >> 6) % (PP * PP);
    int img = idx / (64 * PP * PP);
    if (img >= IMGS) return;
    int pp = pix / PP, qq = pix % PP;
    if (pp != 0 && pp != PP - 1 && qq != 0 && qq != PP - 1) return;
    size_t off = ((size_t)(img * PP * PP) + pix) * PCH + g * 8;
    float4 z = make_float4(0.f, 0.f, 0.f, 0.f);
    *(float4*)&g_P[off] = z;
}

// ---------------- build padded NHWC fp16 from NCHW fp32 --------------------
__global__ void build_nhwc_kernel(const float* __restrict__ src) {
    __shared__ float s[AGENTS][32][33];
    const int tid = threadIdx.x;
    const int px0 = blockIdx.x * 32;
    const int c0 = blockIdx.y * 32;
    const int b = blockIdx.z;

#pragma unroll
    for (int a = 0; a < AGENTS; ++a) {
        for (int e = tid; e < 32 * 32; e += 256) {
            int i = e >> 5, j = e & 31;
            s[a][i][j] =
                src[((size_t)((b * AGENTS + a) * CH + c0 + i)) * HW + px0 + j];
        }
    }
    __syncthreads();

    for (int e = tid; e < 32 * 32; e += 256) {
        int i = e & 31;
        int j = e >> 5;
        int px = px0 + j;
        int py = (px >> 5) + 1, qx = (px & 31) + 1;
        float sum = 0.f;
#pragma unroll
        for (int a = 0; a < AGENTS; ++a) sum += s[a][i][j];
#pragma unroll
        for (int a = 0; a < AGENTS; ++a) {
            float own = s[a][i][j];
            float msg = (sum - own) * (1.0f / (AGENTS - 1));
            size_t base = ((size_t)((b * AGENTS + a) * PP + py) * PP + qx) * PCH;
            g_P[base + c0 + i] = __float2half(own);
            g_P[base + CH + c0 + i] = __float2half(msg);
        }
    }
}

// ---------------- mma.sync conv body ----------------------------------------
// CTA: 128 oc x 128 px, 256 threads (8 warps as 4m x 2n).
// K loop: (ci 64-chunk-pairs) x 9 taps, single fp16 weights, K=64 per stage.
// A/B tiles: 128 rows x 128B, 16B-chunk phys = c ^ (row&7)  [SW128, R10-val].
// Stage = 32KB; THREE stages (dist 2, cp_wait<1>); 2 CTAs/SM.
// Copy issue for stage s+2 is interleaved into the ks-blocks of compute(s):
// no LSU burst at stage start, mma resumes immediately after the barrier.
#define STAGEB 32768
#define SMEMB (3 * STAGEB)          // 98304

template <int CI>
__device__ __forceinline__ void conv_body(
    uint32_t sb, const __half* __restrict__ W,
    const float* __restrict__ bias, float* __restrict__ outb, int ocb) {
    const int tid = threadIdx.x;
    const int lane = tid & 31;
    const int wid = tid >> 5;
    const int wm = wid >> 1;           // 0..3 -> 32-oc slice
    const int wn = wid & 1;            // 0..1 -> 64-px slice
    const int gid = lane >> 2;
    const int tig = lane & 3;

    const int y0 = blockIdx.x * 4;     // image row base
    const int img = blockIdx.z;

    constexpr int S = (CI / 64) * 9;   // 72 or 36 (divisible by 3)
    constexpr int ACI = COUT * CI;     // offA step per tap (elements)

    // ---- copy precompute: thread covers rows r0+32*it, chunk cA (constant)
    const int r0 = tid >> 3;                        // 0..31
    const int cA = tid & 7;
    const uint32_t sw = (uint32_t)((cA ^ (r0 & 7)) << 4);   // row&7 invariant
    const uint32_t dA = (uint32_t)r0 * 128 + sw;    // + it*4096
    const uint32_t dB = 16384u + dA;
    const int aofA = (ocb * 128 + r0) * CI + cA * 8;             // + it*32*CI
    const int bofB = ((img * PP + y0) * PP + r0) * PCH + cA * 8; // + it*PP*PCH

    // ---- ldsm per-lane base offsets (mi/nj: +2048, ks: ^(ks<<5))
    const int lr = lane & 15, hb = lane >> 4;
    const uint32_t aoff0 = (uint32_t)((wm * 32 + lr) * 128) +
                           (uint32_t)((hb ^ (lr & 7)) << 4);
    const uint32_t boff0 = 16384u + (uint32_t)((wn * 64 + lr) * 128) +
                           (uint32_t)((hb ^ (lr & 7)) << 4);

    // ---- incremental stage counters (tap inner, chunk-pair outer)
    int tap_n = 0, kx_n = 0, chunkb = 0, offA = 0, offB = 0;
    auto adv = [&]() {
        if (++tap_n == 9) {
            tap_n = 0; kx_n = 0; chunkb += 64; offA = chunkb; offB = chunkb;
        } else {
            offA += ACI;
            if (++kx_n == 3) { kx_n = 0; offB += (PP - 2) * PCH; }
            else offB += PCH;
        }
    };
    auto issue = [&](uint32_t bb) {           // prologue-only plain issue
#pragma unroll
        for (int it = 0; it < 4; ++it) {
            cp16(bb + dA + it * 4096, W + aofA + it * 32 * CI + offA);
            cp16(bb + dB + it * 4096, g_P + bofB + it * PP * PCH + offB);
        }
        CP_COMMIT();
        adv();
    };

    float d[2][8][4];
#pragma unroll
    for (int mi = 0; mi < 2; ++mi)
#pragma unroll
        for (int ni = 0; ni < 8; ++ni)
#pragma unroll
            for (int k = 0; k < 4; ++k) d[mi][ni][k] = 0.f;

    // ---- fused compute(stage @cbase) + interleaved issue(stage+2 @ibase)
    auto step = [&](uint32_t cbase, uint32_t ibase, bool doIssue) {
#pragma unroll
        for (int ks = 0; ks < 4; ++ks) {
            const uint32_t kxx = (uint32_t)ks << 5;
            uint32_t ah[2][4];
#pragma unroll
            for (int mi = 0; mi < 2; ++mi) {
                uint32_t aaddr = cbase + ((aoff0 + mi * 2048) ^ kxx);
                ldsm4(ah[mi][0], ah[mi][1], ah[mi][2], ah[mi][3], aaddr);
            }
            uint32_t bb[8][2];
#pragma unroll
            for (int nj = 0; nj < 4; ++nj) {
                uint32_t q0, q1, q2, q3;
                ldsm4(q0, q1, q2, q3, cbase + ((boff0 + nj * 2048) ^ kxx));
                bb[nj * 2][0] = q0; bb[nj * 2][1] = q2;
                bb[nj * 2 + 1][0] = q1; bb[nj * 2 + 1][1] = q3;
            }
            if (doIssue) {          // 2 cp16 per ks, spread across the stage
                cp16(ibase + dA + ks * 4096, W + aofA + ks * 32 * CI + offA);
                cp16(ibase + dB + ks * 4096, g_P + bofB + ks * PP * PCH + offB);
            }
#pragma unroll
            for (int mi = 0; mi < 2; ++mi)
#pragma unroll
                for (int ni = 0; ni < 8; ++ni) mma_fp16(d[mi][ni], ah[mi], bb[ni]);
        }
        if (doIssue) { CP_COMMIT(); adv(); }
    };

    const uint32_t b0 = sb, b1 = sb + STAGEB, b2 = sb + 2 * STAGEB;
    issue(b0);                          // stage 0
    issue(b1);                          // stage 1
    int s = 0;
    for (; s + 3 < S; s += 3) {
        cp_wait<1>(); __syncthreads();  // stage s resident + slot b2 free
        step(b0, b2, true);             // compute s,   issue s+2
        cp_wait<1>(); __syncthreads();
        step(b1, b0, true);             // compute s+1, issue s+3
        cp_wait<1>(); __syncthreads();
        step(b2, b1, true);             // compute s+2, issue s+4
    }
    // tail: stages S-3, S-2, S-1 (S divisible by 3)
    cp_wait<1>(); __syncthreads();
    step(b0, b2, true);                 // compute S-3, issue S-1
    cp_wait<1>(); __syncthreads();
    step(b1, 0, false);                 // compute S-2
    cp_wait<0>(); __syncthreads();
    step(b2, 0, false);                 // compute S-1

    // ---- epilogue: fragment -> NCHW + bias
#pragma unroll
    for (int mi = 0; mi < 2; ++mi) {
        int oc_lo = ocb * 128 + wm * 32 + mi * 16 + gid;
        int oc_hi = oc_lo + 8;
        float bz0 = bias[oc_lo];
        float bz1 = bias[oc_hi];
        float* p0 = outb + ((size_t)img * COUT + oc_lo) * HW;
        float* p1 = outb + ((size_t)img * COUT + oc_hi) * HW;
#pragma unroll
        for (int ni = 0; ni < 8; ++ni) {
            int pix = y0 * 32 + wn * 64 + ni * 8 + tig * 2;
            float2 v0 = make_float2(d[mi][ni][0] + bz0, d[mi][ni][1] + bz0);
            float2 v1 = make_float2(d[mi][ni][2] + bz1, d[mi][ni][3] + bz1);
            *(float2*)(p0 + pix) = v0;
            *(float2*)(p1 + pix) = v1;
        }
    }
}

// merged conv, heavy/light interleaved in scheduling order:
//  yq even -> w_ih conv (CI=512) into g_gi, ocb = yq/2
//  yq odd  -> w_hh conv (CI=256) into g_gh, ocb = yq/2
__global__ void __launch_bounds__(256, 2)
conv_both_kernel(const float* __restrict__ b_ih, const float* __restrict__ b_hh) {
    extern __shared__ char smc[];
    const uint32_t sb = smem_u32(smc);
    const int yq = blockIdx.y;
    if ((yq & 1) == 0)
        conv_body<CIN1>(sb, g_wih, b_ih, g_gi, yq >> 1);
    else
        conv_body<CH>(sb, g_whh, b_hh, g_gh, yq >> 1);
}

// ---------------- GRU elementwise ------------------------------------------
__device__ __forceinline__ float sigmoidf_(float x) { return 1.0f / (1.0f + expf(-x)); }
__device__ __forceinline__ float tanhf_(float x) {
    float e = expf(2.0f * x);
    return 1.0f - 2.0f / (e + 1.0f);
}

__global__ void gru_kernel(const float* __restrict__ hsrc, float* __restrict__ dst) {
    int idx = blockIdx.x * blockDim.x + threadIdx.x;   // 48*256*256
    int p4 = idx & 255;
    int c = (idx >> 8) & 255;
    int img = idx >> 16;
    if (img >= IMGS) return;

    const float4* gi4 = (const float4*)g_gi;
    const float4* gh4 = (const float4*)g_gh;

    size_t gbase = (size_t)img * COUT * 256;
    float4 ir = gi4[gbase + (size_t)c * 256 + p4];
    float4 ii = gi4[gbase + (size_t)(CH + c) * 256 + p4];
    float4 in_ = gi4[gbase + (size_t)(2 * CH + c) * 256 + p4];
    float4 hr = gh4[gbase + (size_t)c * 256 + p4];
    float4 hi = gh4[gbase + (size_t)(CH + c) * 256 + p4];
    float4 hn = gh4[gbase + (size_t)(2 * CH + c) * 256 + p4];
    float4 h = ((const float4*)hsrc)[(size_t)(img * CH + c) * 256 + p4];

    float4 o;
    {
        float r = sigmoidf_(ir.x + hr.x), z = sigmoidf_(ii.x + hi.x);
        float n = tanhf_(in_.x + r * hn.x);
        o.x = n + z * (h.x - n);
    }
    {
        float r = sigmoidf_(ir.y + hr.y), z = sigmoidf_(ii.y + hi.y);
        float n = tanhf_(in_.y + r * hn.y);
        o.y = n + z * (h.y - n);
    }
    {
        float r = sigmoidf_(ir.z + hr.z), z = sigmoidf_(ii.z + hi.z);
        float n = tanhf_(in_.z + r * hn.z);
        o.z = n + z * (h.z - n);
    }
    {
        float r = sigmoidf_(ir.w + hr.w), z = sigmoidf_(ii.w + hi.w);
        float n = tanhf_(in_.w + r * hn.w);
        o.w = n + z * (h.w - n);
    }
    ((float4*)dst)[(size_t)(img * CH + c) * 256 + p4] = o;
}

// ---------------- launch ----------------------------------------------------
extern "C" void kernel_launch(void* const* d_in, const int* in_sizes, int n_in,
                              void* d_out, int out_size) {
    const float* x = (const float*)d_in[0];
    const float* w_ih = (const float*)d_in[1];
    const float* w_hh = (const float*)d_in[2];
    const float* b_ih = (const float*)d_in[3];
    const float* b_hh = (const float*)d_in[4];
    float* out = (float*)d_out;

    cudaFuncSetAttribute(conv_both_kernel,
                         cudaFuncAttributeMaxDynamicSharedMemorySize, SMEMB);

    {
        int n = 9 * COUT * CIN1;
        wprep_kernel<<<(n + 255) / 256, 256>>>(w_ih, w_hh);
    }
    {
        int n = IMGS * PP * PP * 64;
        zero_border_kernel<<<(n + 255) / 256, 256>>>();
    }

    dim3 bgrid(32, 8, BATCH);                  // pxtile, ctile, b
    dim3 cgrid(8, 12, IMGS);                   // px-tiles, interleaved oc-tiles
    const int gru_blocks = (IMGS * CH * 256 + 255) / 256;

    for (int it = 0; it < NITER; ++it) {
        const float* src = (it == 0) ? x : out;
        build_nhwc_kernel<<<bgrid, 256>>>(src);
        conv_both_kernel<<<cgrid, 256, SMEMB>>>(b_ih, b_hh);
        gru_kernel<<<gru_blocks, 256>>>(src, out);
    }
}